// round 15
// baseline (speedup 1.0000x reference)
#include <cuda_runtime.h>
#include <cuda_fp16.h>
#include <cstdint>

// DynamicFilter via mma.sync m16n8k16 fp16 with f16 accumulate (2-step windows)
// drained to f32 shadow accumulators + fused 9-tap epilogue.
// CTA=(h,b), 256 thr = 8 warps = 4 M-strips (M=32/warp) x 2 cb-halves (16 cb each).
// Per half: depth-3 cp.async W ring, prefetch distance 1, 128-thr named barrier.

#define CN 256
#define HN 128
#define WN 128
#define HW (HN*WN)

#define XPROWB 544u
#define XPBYTES (128u*XPROWB)        // 69632
#define WROWB 160u
#define WCHUNKB (72u*WROWB)          // 11520
#define SMEM_TOTAL (XPBYTES + 6u*WCHUNKB)   // 69632 + 69120 = 138752

__device__ uint32_t g_wperm[32 * 4 * 72 * 40];

#define CPA16(dst, src) \
    asm volatile("cp.async.cg.shared.global [%0], [%1], 16;" :: "r"(dst), "l"(src) : "memory")
#define CP_COMMIT() asm volatile("cp.async.commit_group;" ::: "memory")
#define CP_WAIT(n)  asm volatile("cp.async.wait_group %0;" :: "n"(n) : "memory")

__device__ __forceinline__ uint32_t smem_u32(const void* p){
    uint32_t a;
    asm("{ .reg .u64 t; cvta.to.shared.u64 t, %1; cvt.u32.u64 %0, t; }" : "=r"(a) : "l"(p));
    return a;
}

__device__ __forceinline__ uint32_t pack_h2(float lo, float hi){
    uint32_t d;
    asm("cvt.rn.f16x2.f32 %0, %1, %2;" : "=r"(d) : "f"(hi), "f"(lo));
    return d;
}

// f16-accumulate mma: window-start form (C = 0) and accumulate form.
__device__ __forceinline__ void mma16h_init(uint32_t* c, const uint32_t* a,
                                            uint32_t b0, uint32_t b1){
    asm volatile(
        "mma.sync.aligned.m16n8k16.row.col.f16.f16.f16.f16 "
        "{%0,%1}, {%2,%3,%4,%5}, {%6,%7}, {%8,%9};"
        : "=r"(c[0]), "=r"(c[1])
        : "r"(a[0]), "r"(a[1]), "r"(a[2]), "r"(a[3]),
          "r"(b0), "r"(b1), "r"(0u), "r"(0u));
}
__device__ __forceinline__ void mma16h_acc(uint32_t* c, const uint32_t* a,
                                           uint32_t b0, uint32_t b1){
    asm volatile(
        "mma.sync.aligned.m16n8k16.row.col.f16.f16.f16.f16 "
        "{%0,%1}, {%2,%3,%4,%5}, {%6,%7}, {%0,%1};"
        : "+r"(c[0]), "+r"(c[1])
        : "r"(a[0]), "r"(a[1]), "r"(a[2]), "r"(a[3]), "r"(b0), "r"(b1));
}

__device__ __forceinline__ void drain2(float& d0, float& d1, uint32_t c){
    float lo, hi;
    asm("{\n .reg .b16 l, h;\n mov.b32 {l, h}, %2;\n"
        " cvt.f32.f16 %0, l;\n cvt.f32.f16 %1, h;\n}"
        : "=f"(lo), "=f"(hi) : "r"(c));
    d0 += lo; d1 += hi;
}

// ---- pre-kernel: permute + fp16-pack W (layout unchanged) ----
__global__ void wperm_kernel(const float* __restrict__ Wm){
    int idx = blockIdx.x * 256 + threadIdx.x;
    if (idx >= 2304 * 128) return;
    int row = idx >> 7, kp = idx & 127;
    int cb = row / 72, r = row % 72;
    int ch = r / 9, p = r % 9;
    int n  = 8 * p + ch;
    int cc = kp >> 5, kpl = kp & 31;
    int s = kpl >> 3, kp8 = kpl & 7;
    int col = 2 * (kp8 & 3) + (kp8 >> 2);
    float e = Wm[row * 256 + 2 * kp];
    float o = Wm[row * 256 + 2 * kp + 1];
    g_wperm[((size_t)(cb * 4 + cc) * 72 + n) * 40 + s * 8 + col] = pack_h2(e, o);
}

extern __shared__ float smf[];

__device__ __forceinline__ void stage_wh(int chunk, uint32_t wd, int tidh){
    const uint32_t* wsrc = g_wperm + (size_t)chunk * (72 * 40);
    #pragma unroll
    for (int i = 0; i < 6; ++i) {
        int slot = tidh + 128 * i;                   // 720 x 16B
        if (slot < 720) CPA16(wd + slot * 16, (const void*)(wsrc + slot * 4));
    }
    CP_COMMIT();
}

__global__ __launch_bounds__(256, 1)
void dynf_mma(const float* __restrict__ x, const float* __restrict__ bias,
              float* __restrict__ out)
{
    const uint32_t sx = smem_u32(smf);

    const int tid  = threadIdx.x;
    const int wid  = tid >> 5;
    const int lane = tid & 31;
    const int g = lane >> 2, q = lane & 3;
    const int half = wid >> 2;                       // 0: cb 0-15, 1: cb 16-31
    const int tidh = tid & 127;
    const int wb   = (wid & 3) * 32;                 // warp's 32-row M strip
    const int h  = blockIdx.x;
    const int bb = blockIdx.y;

    const uint32_t swh = sx + XPBYTES + (uint32_t)half * (3u * WCHUNKB);

    // prefetch my half's chunk 0 into ring slot 0
    stage_wh(half * 64 + 0, swh + 0u * WCHUNKB, tidh);

    // stage X row as packed f16x2 pairs
    {
        const float* xsrc = x + (size_t)bb * CN * HW + (size_t)h * WN;
        #pragma unroll 4
        for (int i = 0; i < 16; ++i) {
            int slot = tid + 256 * i;                // 4096: kp(128) x w4(32)
            int kp = slot >> 5, w4 = slot & 31;
            const float4 e = *(const float4*)(xsrc + (size_t)(2 * kp) * HW + w4 * 4);
            const float4 o = *(const float4*)(xsrc + (size_t)(2 * kp + 1) * HW + w4 * 4);
            uint32_t v0 = pack_h2(e.x, o.x), v1 = pack_h2(e.y, o.y);
            uint32_t v2 = pack_h2(e.z, o.z), v3 = pack_h2(e.w, o.w);
            asm volatile("st.shared.v4.b32 [%0], {%1,%2,%3,%4};"
                         :: "r"(sx + (uint32_t)kp * XPROWB + (uint32_t)w4 * 16),
                            "r"(v0), "r"(v1), "r"(v2), "r"(v3) : "memory");
        }
    }
    __syncthreads();

    // ===== per-half main loop: 16 cb tiles x 4 k64 chunks x (2 windows x 2 k16) =====
    int cur = 0;
    for (int cbl = 0; cbl < 16; ++cbl) {
        const int cb = half * 16 + cbl;
        float facc[9][2][4];                         // f32 shadow accumulators
        #pragma unroll
        for (int j = 0; j < 9; ++j)
            #pragma unroll
            for (int st = 0; st < 2; ++st)
                #pragma unroll
                for (int e = 0; e < 4; ++e) facc[j][st][e] = 0.f;

        for (int cc = 0; cc < 4; ++cc) {
            const int ci = cbl * 4 + cc;             // 0..63 within half
            const int nxt = (cur == 2) ? 0 : cur + 1;
            if (ci + 1 < 64) {
                stage_wh(half * 64 + ci + 1, swh + (uint32_t)nxt * WCHUNKB, tidh);
                CP_WAIT(1);
            } else {
                CP_WAIT(0);
            }
            asm volatile("bar.sync %0, 128;" :: "r"(half + 1) : "memory");

            const uint32_t wbf = swh + (uint32_t)cur * WCHUNKB;
            uint32_t cacc[9][2][2];                  // f16x2 window accumulators
            #pragma unroll
            for (int w2 = 0; w2 < 2; ++w2) {         // two 2-step windows
                #pragma unroll
                for (int s2 = 0; s2 < 2; ++s2) {
                    const int s = w2 * 2 + s2;
                    const uint32_t r0 = sx + (uint32_t)(cc * 32 + s * 8 + q) * XPROWB
                                      + (uint32_t)(wb + g) * 4;
                    uint32_t a0[4], a1[4];
                    asm volatile("ld.shared.b32 %0, [%1];"      : "=r"(a0[0]) : "r"(r0));
                    asm volatile("ld.shared.b32 %0, [%1+32];"   : "=r"(a0[1]) : "r"(r0));
                    asm volatile("ld.shared.b32 %0, [%1+2176];" : "=r"(a0[2]) : "r"(r0));
                    asm volatile("ld.shared.b32 %0, [%1+2208];" : "=r"(a0[3]) : "r"(r0));
                    asm volatile("ld.shared.b32 %0, [%1+64];"   : "=r"(a1[0]) : "r"(r0));
                    asm volatile("ld.shared.b32 %0, [%1+96];"   : "=r"(a1[1]) : "r"(r0));
                    asm volatile("ld.shared.b32 %0, [%1+2240];" : "=r"(a1[2]) : "r"(r0));
                    asm volatile("ld.shared.b32 %0, [%1+2272];" : "=r"(a1[3]) : "r"(r0));
                    #pragma unroll
                    for (int j = 0; j < 9; ++j) {
                        uint32_t b0, b1;
                        const uint32_t baddr = wbf + (uint32_t)(8 * j + g) * WROWB
                                             + (uint32_t)(s * 32 + q * 8);
                        asm volatile("ld.shared.v2.b32 {%0,%1}, [%2];"
                                     : "=r"(b0), "=r"(b1) : "r"(baddr));
                        if (s2 == 0) {
                            mma16h_init(cacc[j][0], a0, b0, b1);
                            mma16h_init(cacc[j][1], a1, b0, b1);
                        } else {
                            mma16h_acc(cacc[j][0], a0, b0, b1);
                            mma16h_acc(cacc[j][1], a1, b0, b1);
                        }
                    }
                }
                // drain window into f32 shadow
                #pragma unroll
                for (int j = 0; j < 9; ++j)
                    #pragma unroll
                    for (int st = 0; st < 2; ++st) {
                        drain2(facc[j][st][0], facc[j][st][1], cacc[j][st][0]);
                        drain2(facc[j][st][2], facc[j][st][3], cacc[j][st][1]);
                    }
            }
            cur = nxt;
        }

        // ---- fused 9-tap epilogue: lane (g,q) owns ch 2q,2q+1 at 4 w positions ----
        #pragma unroll
        for (int b2 = 0; b2 < 2; ++b2) {
            const int ch = 2 * q + b2;
            const int c  = cb * 8 + ch;
            const float* xc = x + (size_t)(bb * CN + c) * HW;
            const float* bp = bias + cb * 72 + ch * 9;
            float res[4] = {0.f, 0.f, 0.f, 0.f};
            const int wpos[4] = { wb + g, wb + g + 8, wb + 16 + g, wb + 24 + g };
            #pragma unroll
            for (int j = 0; j < 9; ++j) {
                const int di = j / 3 - 1, dj = j % 3 - 1;
                const int hh = h + di;
                const bool hok = (hh >= 0) && (hh < HN);
                const float bv = __ldg(bp + j);
                const float* xr = xc + (size_t)hh * WN;
                const float fv[4] = { facc[j][0][b2], facc[j][0][2 + b2],
                                      facc[j][1][b2], facc[j][1][2 + b2] };
                #pragma unroll
                for (int r = 0; r < 4; ++r) {
                    const int ww = wpos[r] + dj;
                    const float xv = (hok && ww >= 0 && ww < WN) ? __ldg(xr + ww) : 0.f;
                    res[r] += (fv[r] + bv) * xv;
                }
            }
            float* orow = out + (size_t)(bb * CN + c) * HW + (size_t)h * WN;
            #pragma unroll
            for (int r = 0; r < 4; ++r) orow[wpos[r]] = res[r];
        }
    }
}

extern "C" void kernel_launch(void* const* d_in, const int* in_sizes, int n_in,
                              void* d_out, int out_size)
{
    const float* x = nullptr; const float* Wm = nullptr; const float* b = nullptr;
    for (int i = 0; i < n_in; ++i) {
        if      (in_sizes[i] == 16777216) x  = (const float*)d_in[i];
        else if (in_sizes[i] == 589824)   Wm = (const float*)d_in[i];
        else if (in_sizes[i] == 2304)     b  = (const float*)d_in[i];
    }
    float* out = (float*)d_out;

    wperm_kernel<<<1152, 256>>>(Wm);

    static int cfg_done = 0;
    if (!cfg_done) {
        cudaFuncSetAttribute(dynf_mma, cudaFuncAttributeMaxDynamicSharedMemorySize,
                             (int)SMEM_TOTAL);
        cfg_done = 1;
    }
    dim3 grid(HN, 4);                 // 512 CTAs: one per (h, b)
    dynf_mma<<<grid, 256, SMEM_TOTAL>>>(x, b, out);
}

// round 16
// speedup vs baseline: 1.2510x; 1.2510x over previous
#include <cuda_runtime.h>
#include <cuda_fp16.h>
#include <cstdint>

// DynamicFilter via mma.sync m16n8k16 fp16 (f32 accum) + fused 9-tap epilogue.
// Grid (h=128, b=4, z=2): CTA does cb tiles [16z, 16z+16) -> 1024 CTAs, 7 waves
// (fixes the 4-wave quantization tail of the 512-CTA version).
// CTA: 256 thr = 8 warps = 4 M-strips (M=32/warp) x 2 cb-halves (8 cb tiles each).
// Per half: depth-3 cp.async W ring, prefetch distance 1, 128-thr named barrier.
// X row staged once as packed f16x2 k-pairs. W pre-permuted by wperm_kernel.

#define CN 256
#define HN 128
#define WN 128
#define HW (HN*WN)

#define XPROWB 544u
#define XPBYTES (128u*XPROWB)        // 69632
#define WROWB 160u
#define WCHUNKB (72u*WROWB)          // 11520
#define SMEM_TOTAL (XPBYTES + 6u*WCHUNKB)   // 69632 + 69120 = 138752

__device__ uint32_t g_wperm[32 * 4 * 72 * 40];   // [cb][cc][n][40 words]

#define CPA16(dst, src) \
    asm volatile("cp.async.cg.shared.global [%0], [%1], 16;" :: "r"(dst), "l"(src) : "memory")
#define CP_COMMIT() asm volatile("cp.async.commit_group;" ::: "memory")
#define CP_WAIT(n)  asm volatile("cp.async.wait_group %0;" :: "n"(n) : "memory")

__device__ __forceinline__ uint32_t smem_u32(const void* p){
    uint32_t a;
    asm("{ .reg .u64 t; cvta.to.shared.u64 t, %1; cvt.u32.u64 %0, t; }" : "=r"(a) : "l"(p));
    return a;
}

__device__ __forceinline__ uint32_t pack_h2(float lo, float hi){
    uint32_t d;
    asm("cvt.rn.f16x2.f32 %0, %1, %2;" : "=r"(d) : "f"(hi), "f"(lo));
    return d;
}

__device__ __forceinline__ void mma16(float* c, const uint32_t* a, uint32_t b0, uint32_t b1){
    asm volatile(
        "mma.sync.aligned.m16n8k16.row.col.f32.f16.f16.f32 "
        "{%0,%1,%2,%3}, {%4,%5,%6,%7}, {%8,%9}, {%0,%1,%2,%3};"
        : "+f"(c[0]), "+f"(c[1]), "+f"(c[2]), "+f"(c[3])
        : "r"(a[0]), "r"(a[1]), "r"(a[2]), "r"(a[3]), "r"(b0), "r"(b1));
}

// ---- pre-kernel: permute + fp16-pack W (layout unchanged) ----
__global__ void wperm_kernel(const float* __restrict__ Wm){
    int idx = blockIdx.x * 256 + threadIdx.x;        // 2304 * 128 total
    if (idx >= 2304 * 128) return;
    int row = idx >> 7, kp = idx & 127;
    int cb = row / 72, r = row % 72;
    int ch = r / 9, p = r % 9;
    int n  = 8 * p + ch;                             // lane-aligned channel remap
    int cc = kp >> 5, kpl = kp & 31;
    int s = kpl >> 3, kp8 = kpl & 7;
    int col = 2 * (kp8 & 3) + (kp8 >> 2);            // pair permutation for v2 loads
    float e = Wm[row * 256 + 2 * kp];
    float o = Wm[row * 256 + 2 * kp + 1];
    g_wperm[((size_t)(cb * 4 + cc) * 72 + n) * 40 + s * 8 + col] = pack_h2(e, o);
}

extern __shared__ float smf[];

__device__ __forceinline__ void stage_wh(int chunk, uint32_t wd, int tidh){
    const uint32_t* wsrc = g_wperm + (size_t)chunk * (72 * 40);
    #pragma unroll
    for (int i = 0; i < 6; ++i) {
        int slot = tidh + 128 * i;                   // 720 x 16B
        if (slot < 720) CPA16(wd + slot * 16, (const void*)(wsrc + slot * 4));
    }
    CP_COMMIT();
}

__global__ __launch_bounds__(256, 1)
void dynf_mma(const float* __restrict__ x, const float* __restrict__ bias,
              float* __restrict__ out)
{
    const uint32_t sx = smem_u32(smf);

    const int tid  = threadIdx.x;
    const int wid  = tid >> 5;
    const int lane = tid & 31;
    const int g = lane >> 2, q = lane & 3;
    const int half = wid >> 2;                       // 0/1 within this CTA's cb range
    const int tidh = tid & 127;
    const int wb   = (wid & 3) * 32;                 // warp's 32-row M strip
    const int h  = blockIdx.x;
    const int bb = blockIdx.y;
    const int zz = blockIdx.z;                       // cb range [16*zz, 16*zz+16)

    const int cb0 = zz * 16 + half * 8;              // this half's first cb tile
    const uint32_t swh = sx + XPBYTES + (uint32_t)half * (3u * WCHUNKB);

    // prefetch my half's chunk 0 into ring slot 0
    stage_wh(cb0 * 4 + 0, swh + 0u * WCHUNKB, tidh);

    // stage X row as packed f16x2 pairs (all 256 threads)
    {
        const float* xsrc = x + (size_t)bb * CN * HW + (size_t)h * WN;
        #pragma unroll 4
        for (int i = 0; i < 16; ++i) {
            int slot = tid + 256 * i;                // 4096: kp(128) x w4(32)
            int kp = slot >> 5, w4 = slot & 31;
            const float4 e = *(const float4*)(xsrc + (size_t)(2 * kp) * HW + w4 * 4);
            const float4 o = *(const float4*)(xsrc + (size_t)(2 * kp + 1) * HW + w4 * 4);
            uint32_t v0 = pack_h2(e.x, o.x), v1 = pack_h2(e.y, o.y);
            uint32_t v2 = pack_h2(e.z, o.z), v3 = pack_h2(e.w, o.w);
            asm volatile("st.shared.v4.b32 [%0], {%1,%2,%3,%4};"
                         :: "r"(sx + (uint32_t)kp * XPROWB + (uint32_t)w4 * 16),
                            "r"(v0), "r"(v1), "r"(v2), "r"(v3) : "memory");
        }
    }
    __syncthreads();                                 // X visible to all

    // ===== per-half main loop: 8 cb tiles x 4 k64 chunks x 4 k16 steps =====
    int cur = 0;                                     // ring slot of current chunk
    for (int cbl = 0; cbl < 8; ++cbl) {
        const int cb = cb0 + cbl;
        float acc[9][2][4];
        #pragma unroll
        for (int j = 0; j < 9; ++j)
            #pragma unroll
            for (int st = 0; st < 2; ++st)
                #pragma unroll
                for (int e = 0; e < 4; ++e) acc[j][st][e] = 0.f;

        for (int cc = 0; cc < 4; ++cc) {
            const int ci = cbl * 4 + cc;             // 0..31 within half
            const int nxt = (cur == 2) ? 0 : cur + 1;
            if (ci + 1 < 32) {
                // slot nxt last read at iter ci-2; barrier at ci-1 separates.
                stage_wh(cb0 * 4 + ci + 1, swh + (uint32_t)nxt * WCHUNKB, tidh);
                CP_WAIT(1);                          // chunk ci complete
            } else {
                CP_WAIT(0);
            }
            asm volatile("bar.sync %0, 128;" :: "r"(half + 1) : "memory");

            const uint32_t wbf = swh + (uint32_t)cur * WCHUNKB;
            #pragma unroll
            for (int s = 0; s < 4; ++s) {            // k16 steps
                const uint32_t r0 = sx + (uint32_t)(cc * 32 + s * 8 + q) * XPROWB
                                  + (uint32_t)(wb + g) * 4;
                uint32_t a0[4], a1[4];
                asm volatile("ld.shared.b32 %0, [%1];"      : "=r"(a0[0]) : "r"(r0));
                asm volatile("ld.shared.b32 %0, [%1+32];"   : "=r"(a0[1]) : "r"(r0));
                asm volatile("ld.shared.b32 %0, [%1+2176];" : "=r"(a0[2]) : "r"(r0));
                asm volatile("ld.shared.b32 %0, [%1+2208];" : "=r"(a0[3]) : "r"(r0));
                asm volatile("ld.shared.b32 %0, [%1+64];"   : "=r"(a1[0]) : "r"(r0));
                asm volatile("ld.shared.b32 %0, [%1+96];"   : "=r"(a1[1]) : "r"(r0));
                asm volatile("ld.shared.b32 %0, [%1+2240];" : "=r"(a1[2]) : "r"(r0));
                asm volatile("ld.shared.b32 %0, [%1+2272];" : "=r"(a1[3]) : "r"(r0));
                #pragma unroll
                for (int j = 0; j < 9; ++j) {
                    uint32_t b0, b1;
                    const uint32_t baddr = wbf + (uint32_t)(8 * j + g) * WROWB
                                         + (uint32_t)(s * 32 + q * 8);
                    asm volatile("ld.shared.v2.b32 {%0,%1}, [%2];"
                                 : "=r"(b0), "=r"(b1) : "r"(baddr));
                    mma16(acc[j][0], a0, b0, b1);
                    mma16(acc[j][1], a1, b0, b1);
                }
            }
            cur = nxt;
        }

        // ---- fused 9-tap epilogue: lane (g,q) owns ch 2q,2q+1 at 4 w positions ----
        #pragma unroll
        for (int b2 = 0; b2 < 2; ++b2) {
            const int ch = 2 * q + b2;
            const int c  = cb * 8 + ch;
            const float* xc = x + (size_t)(bb * CN + c) * HW;
            const float* bp = bias + cb * 72 + ch * 9;
            float res[4] = {0.f, 0.f, 0.f, 0.f};
            const int wpos[4] = { wb + g, wb + g + 8, wb + 16 + g, wb + 24 + g };
            #pragma unroll
            for (int j = 0; j < 9; ++j) {
                const int di = j / 3 - 1, dj = j % 3 - 1;
                const int hh = h + di;
                const bool hok = (hh >= 0) && (hh < HN);
                const float bv = __ldg(bp + j);
                const float* xr = xc + (size_t)hh * WN;
                const float fv[4] = { acc[j][0][b2], acc[j][0][2 + b2],
                                      acc[j][1][b2], acc[j][1][2 + b2] };
                #pragma unroll
                for (int r = 0; r < 4; ++r) {
                    const int ww = wpos[r] + dj;
                    const float xv = (hok && ww >= 0 && ww < WN) ? __ldg(xr + ww) : 0.f;
                    res[r] += (fv[r] + bv) * xv;
                }
            }
            float* orow = out + (size_t)(bb * CN + c) * HW + (size_t)h * WN;
            #pragma unroll
            for (int r = 0; r < 4; ++r) orow[wpos[r]] = res[r];
        }
    }
}

extern "C" void kernel_launch(void* const* d_in, const int* in_sizes, int n_in,
                              void* d_out, int out_size)
{
    const float* x = nullptr; const float* Wm = nullptr; const float* b = nullptr;
    for (int i = 0; i < n_in; ++i) {
        if      (in_sizes[i] == 16777216) x  = (const float*)d_in[i];
        else if (in_sizes[i] == 589824)   Wm = (const float*)d_in[i];
        else if (in_sizes[i] == 2304)     b  = (const float*)d_in[i];
    }
    float* out = (float*)d_out;

    wperm_kernel<<<1152, 256>>>(Wm);

    static int cfg_done = 0;
    if (!cfg_done) {
        cudaFuncSetAttribute(dynf_mma, cudaFuncAttributeMaxDynamicSharedMemorySize,
                             (int)SMEM_TOTAL);
        cfg_done = 1;
    }
    dim3 grid(HN, 4, 2);              // 1024 CTAs: (h, b, cb-half-of-32)
    dynf_mma<<<grid, 256, SMEM_TOTAL>>>(x, b, out);
}

// round 17
// speedup vs baseline: 1.3542x; 1.0825x over previous
#include <cuda_runtime.h>
#include <cuda_fp16.h>
#include <cstdint>

// DynamicFilter via mma.sync m16n8k16 fp16 (f32 accum) + fused 9-tap epilogue.
// Grid (h=128, b=4, z=2); CTA = 16 cb tiles. 8 warps = 4 M-strips (M=32) x
// 2 tap-groups (taps 0-4 / 5-8, templated) -> acc 40 regs -> occupancy 2
// (prologue of one CTA hides under sibling CTA's main loop).
// Single depth-2 W ring, staged post-barrier (race-free). Epilogue: tap-group B
// writes partials to smem scratch, group A combines + stores.

#define CN 256
#define HN 128
#define WN 128
#define HW (HN*WN)

#define XPROWB 544u
#define XPBYTES (128u*XPROWB)        // 69632
#define WROWB 160u
#define WCHUNKB (72u*WROWB)          // 11520
#define SCROWW 132u                  // scratch row stride (words), conflict-free
#define OFF_RING XPBYTES
#define OFF_SCR (XPBYTES + 2u*WCHUNKB)
#define SMEM_TOTAL (OFF_SCR + 8u*SCROWW*4u)   // 69632+23040+4224 = 96896

__device__ uint32_t g_wperm[32 * 4 * 72 * 40];   // [cb][cc][n][40 words]

#define CPA16(dst, src) \
    asm volatile("cp.async.cg.shared.global [%0], [%1], 16;" :: "r"(dst), "l"(src) : "memory")
#define CP_COMMIT() asm volatile("cp.async.commit_group;" ::: "memory")
#define CP_WAIT0()  asm volatile("cp.async.wait_group 0;" ::: "memory")
#define BAR_ALL()   asm volatile("bar.sync 0, 256;" ::: "memory")

__device__ __forceinline__ uint32_t smem_u32(const void* p){
    uint32_t a;
    asm("{ .reg .u64 t; cvta.to.shared.u64 t, %1; cvt.u32.u64 %0, t; }" : "=r"(a) : "l"(p));
    return a;
}

__device__ __forceinline__ uint32_t pack_h2(float lo, float hi){
    uint32_t d;
    asm("cvt.rn.f16x2.f32 %0, %1, %2;" : "=r"(d) : "f"(hi), "f"(lo));
    return d;
}

__device__ __forceinline__ void mma16(float* c, const uint32_t* a, uint32_t b0, uint32_t b1){
    asm volatile(
        "mma.sync.aligned.m16n8k16.row.col.f32.f16.f16.f32 "
        "{%0,%1,%2,%3}, {%4,%5,%6,%7}, {%8,%9}, {%0,%1,%2,%3};"
        : "+f"(c[0]), "+f"(c[1]), "+f"(c[2]), "+f"(c[3])
        : "r"(a[0]), "r"(a[1]), "r"(a[2]), "r"(a[3]), "r"(b0), "r"(b1));
}

// ---- pre-kernel: permute + fp16-pack W (layout unchanged) ----
__global__ void wperm_kernel(const float* __restrict__ Wm){
    int idx = blockIdx.x * 256 + threadIdx.x;        // 2304 * 128 total
    if (idx >= 2304 * 128) return;
    int row = idx >> 7, kp = idx & 127;
    int cb = row / 72, r = row % 72;
    int ch = r / 9, p = r % 9;
    int n  = 8 * p + ch;                             // lane-aligned channel remap
    int cc = kp >> 5, kpl = kp & 31;
    int s = kpl >> 3, kp8 = kpl & 7;
    int col = 2 * (kp8 & 3) + (kp8 >> 2);            // pair permutation for v2 loads
    float e = Wm[row * 256 + 2 * kp];
    float o = Wm[row * 256 + 2 * kp + 1];
    g_wperm[((size_t)(cb * 4 + cc) * 72 + n) * 40 + s * 8 + col] = pack_h2(e, o);
}

extern __shared__ float smf[];

__device__ __forceinline__ void stage_w(int chunk, uint32_t wd, int tid){
    const uint32_t* wsrc = g_wperm + (size_t)chunk * (72 * 40);
    #pragma unroll
    for (int i = 0; i < 3; ++i) {
        int slot = tid + 256 * i;                    // 720 x 16B
        if (slot < 720) CPA16(wd + slot * 16, (const void*)(wsrc + slot * 4));
    }
    CP_COMMIT();
}

// Tap-group main loop: taps [J0, J0+NJ). Group 0 (J0=0) combines + stores.
template<int J0, int NJ>
__device__ __forceinline__ void cb_stream(
    const float* __restrict__ x, const float* __restrict__ bias,
    float* __restrict__ out, uint32_t sx,
    int tid, int wid, int lane, int h, int bb, int cbbase)
{
    const int g = lane >> 2, q = lane & 3;
    const int wb = (wid & 3) * 32;
    const uint32_t ring = sx + OFF_RING;
    const uint32_t scr  = sx + OFF_SCR;

    for (int cbl = 0; cbl < 16; ++cbl) {
        const int cb = cbbase + cbl;
        float acc[NJ][2][4];
        #pragma unroll
        for (int jl = 0; jl < NJ; ++jl)
            #pragma unroll
            for (int st = 0; st < 2; ++st)
                #pragma unroll
                for (int e = 0; e < 4; ++e) acc[jl][st][e] = 0.f;

        for (int cc = 0; cc < 4; ++cc) {
            const int ci = cbl * 4 + cc;             // 0..63
            CP_WAIT0();                              // chunk ci complete
            BAR_ALL();                               // all reads of buf (ci+1)&1 done (iter ci-1)
            if (ci + 1 < 64)                         // post-barrier staging: race-free depth-2
                stage_w(cbbase * 4 + ci + 1, ring + (uint32_t)((ci + 1) & 1) * WCHUNKB, tid);

            const uint32_t wbf = ring + (uint32_t)(ci & 1) * WCHUNKB;
            #pragma unroll
            for (int s = 0; s < 4; ++s) {            // k16 steps
                const uint32_t r0 = sx + (uint32_t)(cc * 32 + s * 8 + q) * XPROWB
                                  + (uint32_t)(wb + g) * 4;
                uint32_t a0[4], a1[4];
                asm volatile("ld.shared.b32 %0, [%1];"      : "=r"(a0[0]) : "r"(r0));
                asm volatile("ld.shared.b32 %0, [%1+32];"   : "=r"(a0[1]) : "r"(r0));
                asm volatile("ld.shared.b32 %0, [%1+2176];" : "=r"(a0[2]) : "r"(r0));
                asm volatile("ld.shared.b32 %0, [%1+2208];" : "=r"(a0[3]) : "r"(r0));
                asm volatile("ld.shared.b32 %0, [%1+64];"   : "=r"(a1[0]) : "r"(r0));
                asm volatile("ld.shared.b32 %0, [%1+96];"   : "=r"(a1[1]) : "r"(r0));
                asm volatile("ld.shared.b32 %0, [%1+2240];" : "=r"(a1[2]) : "r"(r0));
                asm volatile("ld.shared.b32 %0, [%1+2272];" : "=r"(a1[3]) : "r"(r0));
                #pragma unroll
                for (int jl = 0; jl < NJ; ++jl) {
                    const int j = J0 + jl;
                    uint32_t b0, b1;
                    const uint32_t baddr = wbf + (uint32_t)(8 * j + g) * WROWB
                                         + (uint32_t)(s * 32 + q * 8);
                    asm volatile("ld.shared.v2.b32 {%0,%1}, [%2];"
                                 : "=r"(b0), "=r"(b1) : "r"(baddr));
                    mma16(acc[jl][0], a0, b0, b1);
                    mma16(acc[jl][1], a1, b0, b1);
                }
            }
        }

        // ---- epilogue: partial 9-tap contraction over taps [J0, J0+NJ) ----
        float res[2][4];
        const int wpos[4] = { wb + g, wb + g + 8, wb + 16 + g, wb + 24 + g };
        #pragma unroll
        for (int b2 = 0; b2 < 2; ++b2) {
            const int ch = 2 * q + b2;
            const int c  = cb * 8 + ch;
            const float* xc = x + (size_t)(bb * CN + c) * HW;
            const float* bp = bias + cb * 72 + ch * 9;
            #pragma unroll
            for (int r = 0; r < 4; ++r) res[b2][r] = 0.f;
            #pragma unroll
            for (int jl = 0; jl < NJ; ++jl) {
                const int j = J0 + jl;
                const int di = j / 3 - 1, dj = j % 3 - 1;
                const int hh = h + di;
                const bool hok = (hh >= 0) && (hh < HN);
                const float bv = __ldg(bp + j);
                const float* xr = xc + (size_t)hh * WN;
                #pragma unroll
                for (int r = 0; r < 4; ++r) {
                    const int ww = wpos[r] + dj;
                    const float fv = acc[jl][r >> 1][(r & 1) ? (2 + b2) : b2];
                    const float xv = (hok && ww >= 0 && ww < WN) ? __ldg(xr + ww) : 0.f;
                    res[b2][r] += (fv + bv) * xv;
                }
            }
            if (J0 != 0) {   // group B: write partial to scratch (conflict-free stride 132)
                #pragma unroll
                for (int r = 0; r < 4; ++r)
                    asm volatile("st.shared.f32 [%0], %1;"
                        :: "r"(scr + ((uint32_t)ch * SCROWW + (uint32_t)wpos[r]) * 4u),
                           "f"(res[b2][r]) : "memory");
            }
        }
        BAR_ALL();           // B's partials visible to A
        if (J0 == 0) {       // group A: combine + store
            #pragma unroll
            for (int b2 = 0; b2 < 2; ++b2) {
                const int ch = 2 * q + b2;
                const int c  = cb * 8 + ch;
                float* orow = out + (size_t)(bb * CN + c) * HW + (size_t)h * WN;
                #pragma unroll
                for (int r = 0; r < 4; ++r) {
                    float pb;
                    asm volatile("ld.shared.f32 %0, [%1];" : "=f"(pb)
                        : "r"(scr + ((uint32_t)ch * SCROWW + (uint32_t)wpos[r]) * 4u));
                    orow[wpos[r]] = res[b2][r] + pb;
                }
            }
        }
    }
}

__global__ __launch_bounds__(256, 2)
void dynf_mma(const float* __restrict__ x, const float* __restrict__ bias,
              float* __restrict__ out)
{
    const uint32_t sx = smem_u32(smf);
    const int tid  = threadIdx.x;
    const int wid  = tid >> 5;
    const int lane = tid & 31;
    const int h  = blockIdx.x;
    const int bb = blockIdx.y;
    const int cbbase = blockIdx.z * 16;

    // prefetch W chunk 0 into ring slot 0
    stage_w(cbbase * 4 + 0, sx + OFF_RING, tid);

    // stage X row as packed f16x2 pairs
    {
        const float* xsrc = x + (size_t)bb * CN * HW + (size_t)h * WN;
        #pragma unroll 4
        for (int i = 0; i < 16; ++i) {
            int slot = tid + 256 * i;                // 4096: kp(128) x w4(32)
            int kp = slot >> 5, w4 = slot & 31;
            const float4 e = *(const float4*)(xsrc + (size_t)(2 * kp) * HW + w4 * 4);
            const float4 o = *(const float4*)(xsrc + (size_t)(2 * kp + 1) * HW + w4 * 4);
            uint32_t v0 = pack_h2(e.x, o.x), v1 = pack_h2(e.y, o.y);
            uint32_t v2 = pack_h2(e.z, o.z), v3 = pack_h2(e.w, o.w);
            asm volatile("st.shared.v4.b32 [%0], {%1,%2,%3,%4};"
                         :: "r"(sx + (uint32_t)kp * XPROWB + (uint32_t)w4 * 16),
                            "r"(v0), "r"(v1), "r"(v2), "r"(v3) : "memory");
        }
    }
    __syncthreads();

    if (wid < 4) cb_stream<0, 5>(x, bias, out, sx, tid, wid, lane, h, bb, cbbase);
    else         cb_stream<5, 4>(x, bias, out, sx, tid, wid, lane, h, bb, cbbase);
}

extern "C" void kernel_launch(void* const* d_in, const int* in_sizes, int n_in,
                              void* d_out, int out_size)
{
    const float* x = nullptr; const float* Wm = nullptr; const float* b = nullptr;
    for (int i = 0; i < n_in; ++i) {
        if      (in_sizes[i] == 16777216) x  = (const float*)d_in[i];
        else if (in_sizes[i] == 589824)   Wm = (const float*)d_in[i];
        else if (in_sizes[i] == 2304)     b  = (const float*)d_in[i];
    }
    float* out = (float*)d_out;

    wperm_kernel<<<1152, 256>>>(Wm);

    static int cfg_done = 0;
    if (!cfg_done) {
        cudaFuncSetAttribute(dynf_mma, cudaFuncAttributeMaxDynamicSharedMemorySize,
                             (int)SMEM_TOTAL);
        cfg_done = 1;
    }
    dim3 grid(HN, 4, 2);              // 1024 CTAs: (h, b, cb-half-of-32)
    dynf_mma<<<grid, 256, SMEM_TOTAL>>>(x, b, out);
}